// round 4
// baseline (speedup 1.0000x reference)
#include <cuda_runtime.h>
#include <cuda_bf16.h>
#include <math.h>

#define HEADS    8
#define ROW      256         // HEADS * 32 floats, both k and v rows
#define N_MAX    32768
#define SLOTS    256         // bucket slots per node (max expected degree ~55)
#define CAPX     320         // smem edge-id capacity (SLOTS + overflow room)
#define LSTR     9           // padded logit stride (gcd(9,32)=1 -> conflict-free)
#define OVF_MAX  8192

// Static device scratch (zero-initialized at module load; the attn kernel
// self-cleans g_count / g_ovf_cnt so every launch starts from zeroed state).
__device__ int g_count[N_MAX];
__device__ int g_edges[(size_t)N_MAX * SLOTS];   // 20 MB bucketed edge ids
__device__ int g_ovf_cnt;
__device__ int g_ovf[OVF_MAX];

// ---------------- bucket build (single pass, 8 edges/thread) ----------------

__device__ __forceinline__ void scat1(int d, int i) {
    int p = atomicAdd(&g_count[d], 1);
    if (p < SLOTS) g_edges[(size_t)d * SLOTS + p] = i;
    else { int o = atomicAdd(&g_ovf_cnt, 1); if (o < OVF_MAX) g_ovf[o] = i; }
}

__global__ void k_scatter(const int* __restrict__ dst, int E) {
    int i = (blockIdx.x * blockDim.x + threadIdx.x) * 8;
    if (i + 7 < E) {
        int4 a = *(const int4*)(dst + i);
        int4 b = *(const int4*)(dst + i + 4);
        // 8 independent atomics issued back-to-back for max MLP
        int p0 = atomicAdd(&g_count[a.x], 1);
        int p1 = atomicAdd(&g_count[a.y], 1);
        int p2 = atomicAdd(&g_count[a.z], 1);
        int p3 = atomicAdd(&g_count[a.w], 1);
        int p4 = atomicAdd(&g_count[b.x], 1);
        int p5 = atomicAdd(&g_count[b.y], 1);
        int p6 = atomicAdd(&g_count[b.z], 1);
        int p7 = atomicAdd(&g_count[b.w], 1);
        if (p0 < SLOTS) g_edges[(size_t)a.x * SLOTS + p0] = i;
        else { int o = atomicAdd(&g_ovf_cnt, 1); if (o < OVF_MAX) g_ovf[o] = i; }
        if (p1 < SLOTS) g_edges[(size_t)a.y * SLOTS + p1] = i + 1;
        else { int o = atomicAdd(&g_ovf_cnt, 1); if (o < OVF_MAX) g_ovf[o] = i + 1; }
        if (p2 < SLOTS) g_edges[(size_t)a.z * SLOTS + p2] = i + 2;
        else { int o = atomicAdd(&g_ovf_cnt, 1); if (o < OVF_MAX) g_ovf[o] = i + 2; }
        if (p3 < SLOTS) g_edges[(size_t)a.w * SLOTS + p3] = i + 3;
        else { int o = atomicAdd(&g_ovf_cnt, 1); if (o < OVF_MAX) g_ovf[o] = i + 3; }
        if (p4 < SLOTS) g_edges[(size_t)b.x * SLOTS + p4] = i + 4;
        else { int o = atomicAdd(&g_ovf_cnt, 1); if (o < OVF_MAX) g_ovf[o] = i + 4; }
        if (p5 < SLOTS) g_edges[(size_t)b.y * SLOTS + p5] = i + 5;
        else { int o = atomicAdd(&g_ovf_cnt, 1); if (o < OVF_MAX) g_ovf[o] = i + 5; }
        if (p6 < SLOTS) g_edges[(size_t)b.z * SLOTS + p6] = i + 6;
        else { int o = atomicAdd(&g_ovf_cnt, 1); if (o < OVF_MAX) g_ovf[o] = i + 6; }
        if (p7 < SLOTS) g_edges[(size_t)b.w * SLOTS + p7] = i + 7;
        else { int o = atomicAdd(&g_ovf_cnt, 1); if (o < OVF_MAX) g_ovf[o] = i + 7; }
    } else {
        for (int j = i; j < E; j++) scat1(dst[j], j);
    }
}

// ---------------- Main attention kernel ----------------
// One block (256 thr) per destination node. All edge ids + logits in smem.
// Self-cleans g_count[n] (and g_ovf_cnt via block 0) so the next launch
// starts from a zeroed state without a separate k_zero kernel.

__global__ __launch_bounds__(256, 8)
void k_attn(const float* __restrict__ v, const float* __restrict__ kk,
            const float* __restrict__ q, const int* __restrict__ dst,
            float* __restrict__ out) {
    const int n   = blockIdx.x;
    const int tid = threadIdx.x;
    const int w   = tid >> 5;
    const int l   = tid & 31;

    __shared__ int    s_eid[CAPX];
    __shared__ float  s_lg[CAPX * LSTR];
    __shared__ float4 s_red[256];
    __shared__ float  s_inv[HEADS];
    __shared__ int    s_novf;

    int cnt_raw;
    if (tid == 0) {
        cnt_raw = g_count[n];
        g_count[n] = 0;          // self-clean for next launch
        s_novf = cnt_raw;        // broadcast via smem
        if (n == 0) g_ovf_cnt = 0;
    }
    __syncthreads();
    cnt_raw = s_novf;
    int cnt = (cnt_raw < SLOTS) ? cnt_raw : SLOTS;

    for (int j = tid; j < cnt; j += 256)
        s_eid[j] = g_edges[(size_t)n * SLOTS + j];

    if (__builtin_expect(cnt_raw > SLOTS, 0)) {
        // Overflow path: never taken for this data, kept for correctness.
        if (tid == 0) s_novf = 0;
        __syncthreads();
        int total = cnt_raw - SLOTS;   // this node's overflow count (upper bound on scan need)
        (void)total;
        int tot = OVF_MAX;
        for (int o = tid; o < tot; o += 256) {
            int e = g_ovf[o];
            if (e >= 0 && dst[e] == n) {
                int p = atomicAdd(&s_novf, 1);
                if (cnt + p < CAPX) s_eid[cnt + p] = e;
            }
        }
        __syncthreads();
        int x = cnt + s_novf;
        cnt = (x < CAPX) ? x : CAPX;
    }
    __syncthreads();

    // q row for this node, lane's 8-element slice (head = l>>2)
    const float* qp = q + (size_t)n * ROW + l * 8;
    const float4 q0 = *(const float4*)qp;
    const float4 q1 = *(const float4*)(qp + 4);

    // ---- Phase 1: logits (warp-per-edge, 2x LDG.128 + 2 shfl) ----
    {
        int j = w;
        for (; j + 8 < cnt; j += 16) {
            int ea = s_eid[j];
            int eb = s_eid[j + 8];
            const float4* ka = (const float4*)(kk + (size_t)ea * ROW + l * 8);
            const float4* kb = (const float4*)(kk + (size_t)eb * ROW + l * 8);
            float4 a0 = __ldcs(ka), a1 = __ldcs(ka + 1);
            float4 b0 = __ldcs(kb), b1 = __ldcs(kb + 1);
            float da = a0.x*q0.x + a0.y*q0.y + a0.z*q0.z + a0.w*q0.w
                     + a1.x*q1.x + a1.y*q1.y + a1.z*q1.z + a1.w*q1.w;
            float db = b0.x*q0.x + b0.y*q0.y + b0.z*q0.z + b0.w*q0.w
                     + b1.x*q1.x + b1.y*q1.y + b1.z*q1.z + b1.w*q1.w;
            da += __shfl_xor_sync(0xffffffffu, da, 1);
            da += __shfl_xor_sync(0xffffffffu, da, 2);
            db += __shfl_xor_sync(0xffffffffu, db, 1);
            db += __shfl_xor_sync(0xffffffffu, db, 2);
            if ((l & 3) == 0) {
                int h = l >> 2;
                s_lg[j * LSTR + h]       = da * 0.0625f;
                s_lg[(j + 8) * LSTR + h] = db * 0.0625f;
            }
        }
        for (; j < cnt; j += 8) {
            int e = s_eid[j];
            const float4* kr = (const float4*)(kk + (size_t)e * ROW + l * 8);
            float4 a0 = __ldcs(kr), a1 = __ldcs(kr + 1);
            float d = a0.x*q0.x + a0.y*q0.y + a0.z*q0.z + a0.w*q0.w
                    + a1.x*q1.x + a1.y*q1.y + a1.z*q1.z + a1.w*q1.w;
            d += __shfl_xor_sync(0xffffffffu, d, 1);
            d += __shfl_xor_sync(0xffffffffu, d, 2);
            if ((l & 3) == 0)
                s_lg[j * LSTR + (l >> 2)] = d * 0.0625f;
        }
    }
    __syncthreads();

    // ---- Phase 2: per-head softmax (warp w == head w) ----
    {
        float m = -INFINITY;
        for (int j = l; j < cnt; j += 32)
            m = fmaxf(m, s_lg[j * LSTR + w]);
        #pragma unroll
        for (int o = 16; o; o >>= 1)
            m = fmaxf(m, __shfl_xor_sync(0xffffffffu, m, o));
        float s = 0.f;
        for (int j = l; j < cnt; j += 32) {
            float e = __expf(s_lg[j * LSTR + w] - m);
            s_lg[j * LSTR + w] = e;
            s += e;
        }
        #pragma unroll
        for (int o = 16; o; o >>= 1)
            s += __shfl_xor_sync(0xffffffffu, s, o);
        if (l == 0) s_inv[w] = 1.f / fmaxf(s, 1e-9f);
    }
    __syncthreads();

    // ---- Phase 3: value accumulation (float4 column, 4 edges in flight) ----
    const int c  = tid & 63;   // float4 column within 256-float row
    const int eo = tid >> 6;   // edge offset 0..3
    const int h  = c >> 3;
    float4 acc = make_float4(0.f, 0.f, 0.f, 0.f);
    {
        int j = eo;
        for (; j + 4 < cnt; j += 8) {
            int ea = s_eid[j];
            int eb = s_eid[j + 4];
            float wa = s_lg[j * LSTR + h];
            float wb = s_lg[(j + 4) * LSTR + h];
            float4 va = __ldcs((const float4*)(v + (size_t)ea * ROW + c * 4));
            float4 vb = __ldcs((const float4*)(v + (size_t)eb * ROW + c * 4));
            acc.x += wa * va.x + wb * vb.x;
            acc.y += wa * va.y + wb * vb.y;
            acc.z += wa * va.z + wb * vb.z;
            acc.w += wa * va.w + wb * vb.w;
        }
        for (; j < cnt; j += 4) {
            int e = s_eid[j];
            float wt = s_lg[j * LSTR + h];
            float4 vv = __ldcs((const float4*)(v + (size_t)e * ROW + c * 4));
            acc.x += wt * vv.x;
            acc.y += wt * vv.y;
            acc.z += wt * vv.z;
            acc.w += wt * vv.w;
        }
    }
    s_red[tid] = acc;
    __syncthreads();
    if (tid < 64) {
        float4 a0 = s_red[tid];
        float4 a1 = s_red[tid + 64];
        float4 a2 = s_red[tid + 128];
        float4 a3 = s_red[tid + 192];
        float inv = s_inv[tid >> 3];
        float4 r;
        r.x = (a0.x + a1.x + a2.x + a3.x) * inv;
        r.y = (a0.y + a1.y + a2.y + a3.y) * inv;
        r.z = (a0.z + a1.z + a2.z + a3.z) * inv;
        r.w = (a0.w + a1.w + a2.w + a3.w) * inv;
        ((float4*)(out + (size_t)n * ROW))[tid] = r;
    }
}

// ---------------- launch ----------------

extern "C" void kernel_launch(void* const* d_in, const int* in_sizes, int n_in,
                              void* d_out, int out_size) {
    const float* v   = (const float*)d_in[0];
    const float* kk  = (const float*)d_in[1];
    const float* q   = (const float*)d_in[2];
    const int*   dst = (const int*)d_in[3];
    float* out = (float*)d_out;

    const int E = in_sizes[3];
    const int N = in_sizes[2] / ROW;

    k_scatter<<<(E + 2047) / 2048, 256>>>(dst, E);
    k_attn<<<N, 256>>>(v, kk, q, dst, out);
}

// round 5
// speedup vs baseline: 1.7227x; 1.7227x over previous
#include <cuda_runtime.h>
#include <cuda_bf16.h>
#include <math.h>

#define HEADS    8
#define ROW      256         // HEADS * 32 floats, both k and v rows
#define N_MAX    32768
#define SLOTS    256         // bucket slots per node (max expected degree ~55)
#define CAPX     320         // smem edge-id capacity (SLOTS + overflow room)
#define LSTR     9           // padded logit stride (gcd(9,32)=1 -> conflict-free)
#define OVF_MAX  8192

// Static device scratch (zero-initialized at module load; k_attn self-cleans
// g_count / g_ovf_cnt AFTER its first barrier so every launch starts zeroed).
__device__ int g_count[N_MAX];
__device__ int g_edges[(size_t)N_MAX * SLOTS];   // 20 MB bucketed edge ids
__device__ int g_ovf_cnt;
__device__ int g_ovf[OVF_MAX];

// ---------------- bucket build (single pass, 4 edges/thread) ----------------

__global__ void k_scatter(const int* __restrict__ dst, int E) {
    int i = (blockIdx.x * blockDim.x + threadIdx.x) * 4;
    if (i + 3 < E) {
        int4 d = *(const int4*)(dst + i);
        int p0 = atomicAdd(&g_count[d.x], 1);
        int p1 = atomicAdd(&g_count[d.y], 1);
        int p2 = atomicAdd(&g_count[d.z], 1);
        int p3 = atomicAdd(&g_count[d.w], 1);
        if (p0 < SLOTS) g_edges[(size_t)d.x * SLOTS + p0] = i;
        else { int o = atomicAdd(&g_ovf_cnt, 1); if (o < OVF_MAX) g_ovf[o] = i; }
        if (p1 < SLOTS) g_edges[(size_t)d.y * SLOTS + p1] = i + 1;
        else { int o = atomicAdd(&g_ovf_cnt, 1); if (o < OVF_MAX) g_ovf[o] = i + 1; }
        if (p2 < SLOTS) g_edges[(size_t)d.z * SLOTS + p2] = i + 2;
        else { int o = atomicAdd(&g_ovf_cnt, 1); if (o < OVF_MAX) g_ovf[o] = i + 2; }
        if (p3 < SLOTS) g_edges[(size_t)d.w * SLOTS + p3] = i + 3;
        else { int o = atomicAdd(&g_ovf_cnt, 1); if (o < OVF_MAX) g_ovf[o] = i + 3; }
    } else {
        for (int j = i; j < E; j++) {
            int d = dst[j];
            int p = atomicAdd(&g_count[d], 1);
            if (p < SLOTS) g_edges[(size_t)d * SLOTS + p] = j;
            else { int o = atomicAdd(&g_ovf_cnt, 1); if (o < OVF_MAX) g_ovf[o] = j; }
        }
    }
}

// ---------------- Main attention kernel ----------------
// One block (256 thr) per destination node. All edge ids + logits in smem.
// Block start is the R3 structure: every thread reads g_count[n] directly
// (uniform L2 broadcast, no barrier in front of it). Self-clean happens
// after the first barrier, off the critical path.

__global__ __launch_bounds__(256, 8)
void k_attn(const float* __restrict__ v, const float* __restrict__ kk,
            const float* __restrict__ q, const int* __restrict__ dst,
            float* __restrict__ out) {
    const int n   = blockIdx.x;
    const int tid = threadIdx.x;
    const int w   = tid >> 5;
    const int l   = tid & 31;

    __shared__ int    s_eid[CAPX];
    __shared__ float  s_lg[CAPX * LSTR];
    __shared__ float4 s_red[256];
    __shared__ float  s_inv[HEADS];
    __shared__ int    s_novf;

    const int cnt_raw = g_count[n];
    int cnt = (cnt_raw < SLOTS) ? cnt_raw : SLOTS;

    for (int j = tid; j < cnt; j += 256)
        s_eid[j] = g_edges[(size_t)n * SLOTS + j];

    if (__builtin_expect(cnt_raw > SLOTS, 0)) {
        // Overflow path: never taken for this data, kept for correctness.
        if (tid == 0) s_novf = 0;
        __syncthreads();
        int total = g_ovf_cnt;
        if (total > OVF_MAX) total = OVF_MAX;
        for (int o = tid; o < total; o += 256) {
            int e = g_ovf[o];
            if (dst[e] == n) {
                int p = atomicAdd(&s_novf, 1);
                if (cnt + p < CAPX) s_eid[cnt + p] = e;
            }
        }
        __syncthreads();
        int x = cnt + s_novf;
        cnt = (x < CAPX) ? x : CAPX;
    }
    __syncthreads();

    // Self-clean for next launch: every thread has already consumed its read
    // of g_count[n] (used for the loop bound before the barrier), so this
    // store cannot race with them. Off the critical path.
    if (tid == 0) {
        g_count[n] = 0;
        if (n == 0) g_ovf_cnt = 0;
    }

    // q row for this node, lane's 8-element slice (head = l>>2)
    const float* qp = q + (size_t)n * ROW + l * 8;
    const float4 q0 = *(const float4*)qp;
    const float4 q1 = *(const float4*)(qp + 4);

    // ---- Phase 1: logits (warp-per-edge, 2x LDG.128 + 2 shfl) ----
    {
        int j = w;
        for (; j + 8 < cnt; j += 16) {
            int ea = s_eid[j];
            int eb = s_eid[j + 8];
            const float4* ka = (const float4*)(kk + (size_t)ea * ROW + l * 8);
            const float4* kb = (const float4*)(kk + (size_t)eb * ROW + l * 8);
            float4 a0 = __ldcs(ka), a1 = __ldcs(ka + 1);
            float4 b0 = __ldcs(kb), b1 = __ldcs(kb + 1);
            float da = a0.x*q0.x + a0.y*q0.y + a0.z*q0.z + a0.w*q0.w
                     + a1.x*q1.x + a1.y*q1.y + a1.z*q1.z + a1.w*q1.w;
            float db = b0.x*q0.x + b0.y*q0.y + b0.z*q0.z + b0.w*q0.w
                     + b1.x*q1.x + b1.y*q1.y + b1.z*q1.z + b1.w*q1.w;
            da += __shfl_xor_sync(0xffffffffu, da, 1);
            da += __shfl_xor_sync(0xffffffffu, da, 2);
            db += __shfl_xor_sync(0xffffffffu, db, 1);
            db += __shfl_xor_sync(0xffffffffu, db, 2);
            if ((l & 3) == 0) {
                int h = l >> 2;
                s_lg[j * LSTR + h]       = da * 0.0625f;
                s_lg[(j + 8) * LSTR + h] = db * 0.0625f;
            }
        }
        for (; j < cnt; j += 8) {
            int e = s_eid[j];
            const float4* kr = (const float4*)(kk + (size_t)e * ROW + l * 8);
            float4 a0 = __ldcs(kr), a1 = __ldcs(kr + 1);
            float d = a0.x*q0.x + a0.y*q0.y + a0.z*q0.z + a0.w*q0.w
                    + a1.x*q1.x + a1.y*q1.y + a1.z*q1.z + a1.w*q1.w;
            d += __shfl_xor_sync(0xffffffffu, d, 1);
            d += __shfl_xor_sync(0xffffffffu, d, 2);
            if ((l & 3) == 0)
                s_lg[j * LSTR + (l >> 2)] = d * 0.0625f;
        }
    }
    __syncthreads();

    // ---- Phase 2: per-head softmax (warp w == head w) ----
    {
        float m = -INFINITY;
        for (int j = l; j < cnt; j += 32)
            m = fmaxf(m, s_lg[j * LSTR + w]);
        #pragma unroll
        for (int o = 16; o; o >>= 1)
            m = fmaxf(m, __shfl_xor_sync(0xffffffffu, m, o));
        float s = 0.f;
        for (int j = l; j < cnt; j += 32) {
            float e = __expf(s_lg[j * LSTR + w] - m);
            s_lg[j * LSTR + w] = e;
            s += e;
        }
        #pragma unroll
        for (int o = 16; o; o >>= 1)
            s += __shfl_xor_sync(0xffffffffu, s, o);
        if (l == 0) s_inv[w] = 1.f / fmaxf(s, 1e-9f);
    }
    __syncthreads();

    // ---- Phase 3: value accumulation (float4 column, 4 edges in flight) ----
    const int c  = tid & 63;   // float4 column within 256-float row
    const int eo = tid >> 6;   // edge offset 0..3
    const int h  = c >> 3;
    float4 acc = make_float4(0.f, 0.f, 0.f, 0.f);
    {
        int j = eo;
        for (; j + 4 < cnt; j += 8) {
            int ea = s_eid[j];
            int eb = s_eid[j + 4];
            float wa = s_lg[j * LSTR + h];
            float wb = s_lg[(j + 4) * LSTR + h];
            float4 va = __ldcs((const float4*)(v + (size_t)ea * ROW + c * 4));
            float4 vb = __ldcs((const float4*)(v + (size_t)eb * ROW + c * 4));
            acc.x += wa * va.x + wb * vb.x;
            acc.y += wa * va.y + wb * vb.y;
            acc.z += wa * va.z + wb * vb.z;
            acc.w += wa * va.w + wb * vb.w;
        }
        for (; j < cnt; j += 4) {
            int e = s_eid[j];
            float wt = s_lg[j * LSTR + h];
            float4 vv = __ldcs((const float4*)(v + (size_t)e * ROW + c * 4));
            acc.x += wt * vv.x;
            acc.y += wt * vv.y;
            acc.z += wt * vv.z;
            acc.w += wt * vv.w;
        }
    }
    s_red[tid] = acc;
    __syncthreads();
    if (tid < 64) {
        float4 a0 = s_red[tid];
        float4 a1 = s_red[tid + 64];
        float4 a2 = s_red[tid + 128];
        float4 a3 = s_red[tid + 192];
        float inv = s_inv[tid >> 3];
        float4 r;
        r.x = (a0.x + a1.x + a2.x + a3.x) * inv;
        r.y = (a0.y + a1.y + a2.y + a3.y) * inv;
        r.z = (a0.z + a1.z + a2.z + a3.z) * inv;
        r.w = (a0.w + a1.w + a2.w + a3.w) * inv;
        ((float4*)(out + (size_t)n * ROW))[tid] = r;
    }
}

// ---------------- launch ----------------

extern "C" void kernel_launch(void* const* d_in, const int* in_sizes, int n_in,
                              void* d_out, int out_size) {
    const float* v   = (const float*)d_in[0];
    const float* kk  = (const float*)d_in[1];
    const float* q   = (const float*)d_in[2];
    const int*   dst = (const int*)d_in[3];
    float* out = (float*)d_out;

    const int E = in_sizes[3];
    const int N = in_sizes[2] / ROW;

    k_scatter<<<(E + 1023) / 1024, 256>>>(dst, E);
    k_attn<<<N, 256>>>(v, kk, q, dst, out);
}